// round 11
// baseline (speedup 1.0000x reference)
#include <cuda_runtime.h>
#include <stdint.h>

#define KTAPS 27
#define SELF_K 13        // (0,0,0) offset: pair_in == row, mask == 1 always
#define CCH 64
#define TILE 16          // rows per block in main kernel
#define THREADS 256
#define MAXN 1048576     // scratch capacity (rows)

#define PROBE_BLOCKS 8   // 8*256 = 2048 samples per slot

// cfg: [0]=mask_kind (0 = 4-byte nonzero test, 1 = 2-byte/bf16 nonzero test)
//      [1]=mask_slot  [2]=pin_slot  [3]=pin_width (4 or 8)
__device__ int g_cfg[4];
__device__ unsigned g_bits[MAXN];   // per-row neighbor-tap bitmask (bit13 unused)
// cross-block probe accumulators (zero-initialized; last block re-zeroes
// after deciding, so every graph replay starts clean)
__device__ unsigned g_cnt[3][5];
__device__ unsigned g_done;

#define F32_ONE   0x3F800000u
#define BF16_ONE  0x3F80

// ---------------- probe + decide: multi-block, single launch ----------------
__global__ void kprobe_decide(const void* c0, const void* c1, const void* c2, int N)
{
    const void* cand[3] = {c0, c1, c2};
    const int t = threadIdx.x;
    const unsigned e = (unsigned)(blockIdx.x * blockDim.x + t);   // < 2048 << N

    unsigned acc[3][5];
    #pragma unroll
    for (int s = 0; s < 3; s++) {
        const unsigned w = ((const unsigned*)cand[s])[e];
        const uint16_t h = (uint16_t)(w & 0xFFFFu);
        const bool maskpat = (w == 0u) || (w == 1u) || (w == F32_ONE) ||
                             (w == 0x3F803F80u) || (w == 0x00003F80u);
        acc[s][0] = !maskpat;
        acc[s][1] = (w == 1u);
        acc[s][2] = (h == BF16_ONE);
        acc[s][3] = (w != 0u && w != e);          // tap0: pair_out == e
        // self-tap arange check (i32 view) on first 256 elements
        unsigned abad = 0;
        if (e < 256) {
            const unsigned a = ((const unsigned*)cand[s])[13u * (unsigned)N + e];
            abad = (a != e);
        }
        acc[s][4] = abad;
    }

    const int lane = t & 31;
    #pragma unroll
    for (int s = 0; s < 3; s++)
        #pragma unroll
        for (int i = 0; i < 5; i++) {
            unsigned v = __reduce_add_sync(0xFFFFFFFFu, acc[s][i]);
            if (lane == 0 && v) atomicAdd(&g_cnt[s][i], v);
        }

    // last-block-decides (atomic ticket); then reset counters for next replay
    __syncthreads();
    __shared__ unsigned is_last;
    if (t == 0) {
        __threadfence();
        is_last = (atomicAdd(&g_done, 1u) == gridDim.x - 1u);
    }
    __syncthreads();
    if (is_last && t == 0) {
        int ms = -1;
        for (int s = 0; s < 3; s++)
            if (g_cnt[s][0] == 0 && ms < 0) ms = s;
        if (ms < 0) ms = 2;
        int mk = (g_cnt[ms][1] == 0 && g_cnt[ms][2] > 0) ? 1 : 0;
        int pa = -1, pb = -1;
        for (int s = 0; s < 3; s++) if (s != ms) { if (pa < 0) pa = s; else pb = s; }
        int pw  = (g_cnt[pa][4] == 0 && g_cnt[pb][4] == 0) ? 4 : 8;
        int pin = (g_cnt[pa][3] >= g_cnt[pb][3]) ? pa : pb;
        g_cfg[0] = mk; g_cfg[1] = ms; g_cfg[2] = pin; g_cfg[3] = pw;
        // reset for next graph replay (ordered after all adds of this launch)
        for (int s = 0; s < 3; s++)
            for (int i = 0; i < 5; i++) g_cnt[s][i] = 0u;
        g_done = 0u;
        __threadfence();
    }
}

// ---------------- mask -> bitmask precompute ----------------
// One thread per row; 26 independent fully-coalesced strided loads (MLP=26),
// one coalesced bitmask store. Pure streaming.
__global__ __launch_bounds__(256)
void kbits(const void* c0, const void* c1, const void* c2, int n)
{
    const void* cand[3] = {c0, c1, c2};
    const int   mk    = g_cfg[0];
    const void* maskp = cand[g_cfg[1] & 3];

    const int row = blockIdx.x * 256 + threadIdx.x;
    if (row >= n) return;

    unsigned bits = 0u;
    if (mk == 0) {
        const unsigned* m32 = (const unsigned*)maskp;
        #pragma unroll
        for (int kk = 0; kk < 26; kk++) {
            const int k = kk + (kk >= SELF_K);
            if (__ldcs(m32 + (size_t)k * (size_t)n + row)) bits |= 1u << k;
        }
    } else {
        const unsigned short* m16 = (const unsigned short*)maskp;
        #pragma unroll
        for (int kk = 0; kk < 26; kk++) {
            const int k = kk + (kk >= SELF_K);
            if (__ldcs(m16 + (size_t)k * (size_t)n + row)) bits |= 1u << k;
        }
    }
    g_bits[row] = bits;
}

// ---------------- main kernel: no smem, no barriers, no atomics ----------------
__global__ __launch_bounds__(THREADS)
void spdwconv_kernel(const float* __restrict__ features,
                     const float* __restrict__ weight,   // [27*64], L1-resident
                     const float* __restrict__ bias,     // [64]
                     const void* c0, const void* c1, const void* c2,
                     float* __restrict__ out,
                     int n)
{
    const void* cand[3] = {c0, c1, c2};
    const int   pw   = g_cfg[3];
    const void* pinp = cand[g_cfg[2] & 3];

    const int t  = threadIdx.x;
    const int r  = t >> 4;        // row within tile (0..15)
    const int c4 = t & 15;        // float4 channel group
    const int nn = blockIdx.x * TILE + r;
    if (nn >= n) return;

    const unsigned b = g_bits[nn];          // broadcast across the half-warp
    float4 acc = reinterpret_cast<const float4*>(bias)[c4];
    unsigned blo = b & ((1u << SELF_K) - 1u);
    unsigned bhi = b >> (SELF_K + 1);

    // taps 0..12 (ascending, deterministic)
    while (blo) {
        const int k = __ffs(blo) - 1;
        blo &= blo - 1;
        const int j = (pw == 4)
            ? __ldg((const int*)pinp + (size_t)k * (size_t)n + nn)
            : (int)__ldg((const long long*)pinp + (size_t)k * (size_t)n + nn);
        const float4 fv = reinterpret_cast<const float4*>(features)[(size_t)j * 16 + c4];
        const float4 wv = reinterpret_cast<const float4*>(weight)[k * 16 + c4];
        acc.x = fmaf(fv.x, wv.x, acc.x);
        acc.y = fmaf(fv.y, wv.y, acc.y);
        acc.z = fmaf(fv.z, wv.z, acc.z);
        acc.w = fmaf(fv.w, wv.w, acc.w);
    }

    // self tap (k = 13): coalesced feature read, transient registers only
    {
        const float4 fv = reinterpret_cast<const float4*>(features)[(size_t)nn * 16 + c4];
        const float4 wv = reinterpret_cast<const float4*>(weight)[SELF_K * 16 + c4];
        acc.x = fmaf(fv.x, wv.x, acc.x);
        acc.y = fmaf(fv.y, wv.y, acc.y);
        acc.z = fmaf(fv.z, wv.z, acc.z);
        acc.w = fmaf(fv.w, wv.w, acc.w);
    }

    // taps 14..26
    while (bhi) {
        const int kb = __ffs(bhi) - 1;
        bhi &= bhi - 1;
        const int k = kb + SELF_K + 1;
        const int j = (pw == 4)
            ? __ldg((const int*)pinp + (size_t)k * (size_t)n + nn)
            : (int)__ldg((const long long*)pinp + (size_t)k * (size_t)n + nn);
        const float4 fv = reinterpret_cast<const float4*>(features)[(size_t)j * 16 + c4];
        const float4 wv = reinterpret_cast<const float4*>(weight)[k * 16 + c4];
        acc.x = fmaf(fv.x, wv.x, acc.x);
        acc.y = fmaf(fv.y, wv.y, acc.y);
        acc.z = fmaf(fv.z, wv.z, acc.z);
        acc.w = fmaf(fv.w, wv.w, acc.w);
    }

    // Output is write-once: stream it past L2.
    __stcs(reinterpret_cast<float4*>(out) + (size_t)nn * 16 + c4, acc);
}

extern "C" void kernel_launch(void* const* d_in, const int* in_sizes, int n_in,
                              void* d_out, int out_size)
{
    int fi = -1, wi = -1, bi = -1;
    int big[3], nbig = 0;
    long long maxc = -1;
    for (int i = 0; i < n_in; i++)
        if ((long long)in_sizes[i] > maxc) { maxc = in_sizes[i]; fi = i; }
    for (int i = 0; i < n_in; i++) {
        if (i == fi) continue;
        if (in_sizes[i] == 64) bi = i;
        else if (in_sizes[i] == KTAPS * CCH) wi = i;
        else if (nbig < 3) big[nbig++] = i;
    }
    const float* features = (const float*)d_in[fi];
    const float* weight   = (const float*)d_in[wi];
    const float* bias     = (const float*)d_in[bi];
    const void*  c0 = d_in[big[0]];
    const void*  c1 = d_in[big[1]];
    const void*  c2 = d_in[big[2]];
    float* out = (float*)d_out;

    const int n = in_sizes[fi] / CCH;

    kprobe_decide<<<PROBE_BLOCKS, 256>>>(c0, c1, c2, n);
    kbits<<<(n + 255) / 256, 256>>>(c0, c1, c2, n);

    const int grid = (n + TILE - 1) / TILE;
    spdwconv_kernel<<<grid, THREADS>>>(features, weight, bias, c0, c1, c2, out, n);
}

// round 12
// speedup vs baseline: 1.3830x; 1.3830x over previous
#include <cuda_runtime.h>
#include <stdint.h>

#define KTAPS 27
#define SELF_K 13        // (0,0,0) offset: pair_in == row, mask == 1 always
#define CCH 64
#define TILE 16          // rows per block in main kernel
#define THREADS 256
#define MAXN 1048576     // scratch capacity (rows)

#define F32_ONE   0x3F800000u

__device__ unsigned g_bits[MAXN];   // per-row neighbor-tap bitmask (bit13 unused)

// ---------------- mask -> bitmask precompute ----------------
// Inline mask-kind detection: all blocks read the SAME fixed words (self-tap
// row 0 is always "one") -> identical decision everywhere, deterministic,
// L2/L1-broadcast after the first block. No separate probe kernel.
__global__ __launch_bounds__(256)
void kbits(const void* maskp, int n)
{
    const unsigned* m32 = (const unsigned*)maskp;
    // self-tap, row 0 (4-byte view): i32 mask -> 1, f32 mask -> F32_ONE
    const unsigned w = __ldg(m32 + (size_t)SELF_K * (size_t)n);
    int mk = 0;                                   // 0 = 4-byte elements
    if (w != 1u && w != F32_ONE) {
        // maybe bf16 (2-byte): self-tap starts at halfword 13n -> word 13n/2
        const unsigned w2 = __ldg(m32 + ((size_t)SELF_K * (size_t)n) / 2);
        if ((w2 & 0xFFFFu) == 0x3F80u) mk = 1;    // 1 = 2-byte elements
    }

    const int row = blockIdx.x * 256 + threadIdx.x;
    if (row >= n) return;

    unsigned bits = 0u;
    if (mk == 0) {
        #pragma unroll
        for (int kk = 0; kk < 26; kk++) {
            const int k = kk + (kk >= SELF_K);
            if (__ldcs(m32 + (size_t)k * (size_t)n + row)) bits |= 1u << k;
        }
    } else {
        const unsigned short* m16 = (const unsigned short*)maskp;
        #pragma unroll
        for (int kk = 0; kk < 26; kk++) {
            const int k = kk + (kk >= SELF_K);
            if (__ldcs(m16 + (size_t)k * (size_t)n + row)) bits |= 1u << k;
        }
    }
    g_bits[row] = bits;
}

// ---------------- main kernel: no smem, no barriers, no atomics ----------------
__global__ __launch_bounds__(THREADS)
void spdwconv_kernel(const float* __restrict__ features,
                     const float* __restrict__ weight,   // [27*64], L1-resident
                     const float* __restrict__ bias,     // [64]
                     const void* __restrict__ pinp,      // pair_in (width probed)
                     float* __restrict__ out,
                     int n)
{
    // Inline pin-width detection: self-tap arange. An int64 array cannot have
    // i32 words (1,2) at these positions; all blocks read the same words.
    const int* p32 = (const int*)pinp;
    const bool pw4 = (__ldg(p32 + (size_t)SELF_K * (size_t)n + 1) == 1) &&
                     (__ldg(p32 + (size_t)SELF_K * (size_t)n + 2) == 2);

    const int t  = threadIdx.x;
    const int r  = t >> 4;        // row within tile (0..15)
    const int c4 = t & 15;        // float4 channel group
    const int nn = blockIdx.x * TILE + r;
    if (nn >= n) return;

    const unsigned b = g_bits[nn];          // broadcast across the half-warp
    float4 acc = reinterpret_cast<const float4*>(bias)[c4];
    unsigned blo = b & ((1u << SELF_K) - 1u);
    unsigned bhi = b >> (SELF_K + 1);

    // taps 0..12 (ascending, deterministic)
    while (blo) {
        const int k = __ffs(blo) - 1;
        blo &= blo - 1;
        const int j = pw4
            ? __ldg(p32 + (size_t)k * (size_t)n + nn)
            : (int)__ldg((const long long*)pinp + (size_t)k * (size_t)n + nn);
        const float4 fv = reinterpret_cast<const float4*>(features)[(size_t)j * 16 + c4];
        const float4 wv = reinterpret_cast<const float4*>(weight)[k * 16 + c4];
        acc.x = fmaf(fv.x, wv.x, acc.x);
        acc.y = fmaf(fv.y, wv.y, acc.y);
        acc.z = fmaf(fv.z, wv.z, acc.z);
        acc.w = fmaf(fv.w, wv.w, acc.w);
    }

    // self tap (k = 13): coalesced feature read, transient registers only
    {
        const float4 fv = reinterpret_cast<const float4*>(features)[(size_t)nn * 16 + c4];
        const float4 wv = reinterpret_cast<const float4*>(weight)[SELF_K * 16 + c4];
        acc.x = fmaf(fv.x, wv.x, acc.x);
        acc.y = fmaf(fv.y, wv.y, acc.y);
        acc.z = fmaf(fv.z, wv.z, acc.z);
        acc.w = fmaf(fv.w, wv.w, acc.w);
    }

    // taps 14..26
    while (bhi) {
        const int kb = __ffs(bhi) - 1;
        bhi &= bhi - 1;
        const int k = kb + SELF_K + 1;
        const int j = pw4
            ? __ldg(p32 + (size_t)k * (size_t)n + nn)
            : (int)__ldg((const long long*)pinp + (size_t)k * (size_t)n + nn);
        const float4 fv = reinterpret_cast<const float4*>(features)[(size_t)j * 16 + c4];
        const float4 wv = reinterpret_cast<const float4*>(weight)[k * 16 + c4];
        acc.x = fmaf(fv.x, wv.x, acc.x);
        acc.y = fmaf(fv.y, wv.y, acc.y);
        acc.z = fmaf(fv.z, wv.z, acc.z);
        acc.w = fmaf(fv.w, wv.w, acc.w);
    }

    // Output is write-once: stream it past L2.
    __stcs(reinterpret_cast<float4*>(out) + (size_t)nn * 16 + c4, acc);
}

extern "C" void kernel_launch(void* const* d_in, const int* in_sizes, int n_in,
                              void* d_out, int out_size)
{
    // Inputs in metadata order: features, weight, bias, pair_in, pair_out,
    // pair_mask. Identify by element count; the three 27*N arrays keep their
    // metadata order (pair_in, pair_out, pair_mask).
    int fi = -1, wi = -1, bi = -1;
    int big[3], nbig = 0;
    long long maxc = -1;
    for (int i = 0; i < n_in; i++)
        if ((long long)in_sizes[i] > maxc) { maxc = in_sizes[i]; fi = i; }
    for (int i = 0; i < n_in; i++) {
        if (i == fi) continue;
        if (in_sizes[i] == 64) bi = i;
        else if (in_sizes[i] == KTAPS * CCH) wi = i;
        else if (nbig < 3) big[nbig++] = i;
    }
    const float* features = (const float*)d_in[fi];
    const float* weight   = (const float*)d_in[wi];
    const float* bias     = (const float*)d_in[bi];
    const void*  pinp     = d_in[big[0]];   // pair_in
    // big[1] = pair_out (unused: scatter target == row under mask)
    const void*  maskp    = d_in[big[2]];   // pair_mask
    float* out = (float*)d_out;

    const int n = in_sizes[fi] / CCH;

    kbits<<<(n + 255) / 256, 256>>>(maskp, n);

    const int grid = (n + TILE - 1) / TILE;
    spdwconv_kernel<<<grid, THREADS>>>(features, weight, bias, pinp, out, n);
}

// round 13
// speedup vs baseline: 1.3869x; 1.0028x over previous
#include <cuda_runtime.h>
#include <stdint.h>

#define KTAPS 27
#define SELF_K 13        // (0,0,0) offset: pair_in == row, mask == 1 always
#define CCH 64
#define TILE 16          // rows per block in main kernel
#define THREADS 256
#define MAXN 1048576     // scratch capacity (rows)

#define F32_ONE   0x3F800000u

// Per-row packed info: {neighbor bits (bit13 unused), j0, j1, j2} where
// j0..j2 are pair_in indices of the first (ascending k) set neighbor taps.
__device__ uint4 g_info[MAXN];

// ---------------- mask -> {bits, j0..j2} precompute ----------------
// Inline width detection: all blocks read the SAME fixed words (self-tap row 0
// mask is always "one"; self-tap pair_in is arange) -> identical decision
// everywhere, deterministic, L1/L2-broadcast. No separate probe kernel.
__global__ __launch_bounds__(256)
void kbits(const void* __restrict__ maskp, const void* __restrict__ pinp, int n)
{
    const unsigned* m32 = (const unsigned*)maskp;
    const unsigned w = __ldg(m32 + (size_t)SELF_K * (size_t)n);
    int mk = 0;                                   // 0 = 4-byte mask elements
    if (w != 1u && w != F32_ONE) {
        const unsigned w2 = __ldg(m32 + ((size_t)SELF_K * (size_t)n) / 2);
        if ((w2 & 0xFFFFu) == 0x3F80u) mk = 1;    // 1 = 2-byte (bf16) mask
    }
    const int* p32 = (const int*)pinp;
    const bool pw4 = (__ldg(p32 + (size_t)SELF_K * (size_t)n + 1) == 1) &&
                     (__ldg(p32 + (size_t)SELF_K * (size_t)n + 2) == 2);

    const int row = blockIdx.x * 256 + threadIdx.x;
    if (row >= n) return;

    unsigned bits = 0u;
    if (mk == 0) {
        #pragma unroll
        for (int kk = 0; kk < 26; kk++) {
            const int k = kk + (kk >= SELF_K);
            if (__ldcs(m32 + (size_t)k * (size_t)n + row)) bits |= 1u << k;
        }
    } else {
        const unsigned short* m16 = (const unsigned short*)maskp;
        #pragma unroll
        for (int kk = 0; kk < 26; kk++) {
            const int k = kk + (kk >= SELF_K);
            if (__ldcs(m16 + (size_t)k * (size_t)n + row)) bits |= 1u << k;
        }
    }

    // Fetch pair_in for the first <=3 set neighbor taps (ascending k).
    // P(>3 neighbors) ~ 6e-4: overflow taps are read directly by the main
    // kernel (order preserved by ascending-k consumption there).
    unsigned j0 = 0, j1 = 0, j2 = 0;
    unsigned bb = bits;
    int cnt = 0;
    while (bb && cnt < 3) {
        const int k = __ffs(bb) - 1;
        bb &= bb - 1;
        const unsigned j = pw4
            ? (unsigned)__ldg(p32 + (size_t)k * (size_t)n + row)
            : (unsigned)__ldg((const long long*)pinp + (size_t)k * (size_t)n + row);
        if (cnt == 0) j0 = j; else if (cnt == 1) j1 = j; else j2 = j;
        cnt++;
    }
    g_info[row] = make_uint4(bits, j0, j1, j2);
}

// ---------------- main kernel: no smem, no barriers, no atomics ----------------
__global__ __launch_bounds__(THREADS)
void spdwconv_kernel(const float* __restrict__ features,
                     const float* __restrict__ weight,   // [27*64], L1-resident
                     const float* __restrict__ bias,     // [64]
                     const void* __restrict__ pinp,      // pair_in (overflow only)
                     float* __restrict__ out,
                     int n)
{
    const int* p32 = (const int*)pinp;
    const bool pw4 = (__ldg(p32 + (size_t)SELF_K * (size_t)n + 1) == 1) &&
                     (__ldg(p32 + (size_t)SELF_K * (size_t)n + 2) == 2);

    const int t  = threadIdx.x;
    const int r  = t >> 4;        // row within tile (0..15)
    const int c4 = t & 15;        // float4 channel group
    const int nn = blockIdx.x * TILE + r;
    if (nn >= n) return;

    const uint4 info = g_info[nn];          // one 16B load: bits + j0..j2
    float4 acc = reinterpret_cast<const float4*>(bias)[c4];
    unsigned blo = info.x & ((1u << SELF_K) - 1u);
    unsigned bhi = info.x >> (SELF_K + 1);
    int cnt = 0;

    // taps 0..12 (ascending, deterministic)
    while (blo) {
        const int k = __ffs(blo) - 1;
        blo &= blo - 1;
        int j;
        if      (cnt == 0) j = (int)info.y;
        else if (cnt == 1) j = (int)info.z;
        else if (cnt == 2) j = (int)info.w;
        else j = pw4 ? __ldg(p32 + (size_t)k * (size_t)n + nn)
                     : (int)__ldg((const long long*)pinp + (size_t)k * (size_t)n + nn);
        cnt++;
        const float4 fv = reinterpret_cast<const float4*>(features)[(size_t)j * 16 + c4];
        const float4 wv = reinterpret_cast<const float4*>(weight)[k * 16 + c4];
        acc.x = fmaf(fv.x, wv.x, acc.x);
        acc.y = fmaf(fv.y, wv.y, acc.y);
        acc.z = fmaf(fv.z, wv.z, acc.z);
        acc.w = fmaf(fv.w, wv.w, acc.w);
    }

    // self tap (k = 13): coalesced feature read, transient registers only
    {
        const float4 fv = reinterpret_cast<const float4*>(features)[(size_t)nn * 16 + c4];
        const float4 wv = reinterpret_cast<const float4*>(weight)[SELF_K * 16 + c4];
        acc.x = fmaf(fv.x, wv.x, acc.x);
        acc.y = fmaf(fv.y, wv.y, acc.y);
        acc.z = fmaf(fv.z, wv.z, acc.z);
        acc.w = fmaf(fv.w, wv.w, acc.w);
    }

    // taps 14..26 (cnt continues ascending-k order across the split)
    while (bhi) {
        const int kb = __ffs(bhi) - 1;
        bhi &= bhi - 1;
        const int k = kb + SELF_K + 1;
        int j;
        if      (cnt == 0) j = (int)info.y;
        else if (cnt == 1) j = (int)info.z;
        else if (cnt == 2) j = (int)info.w;
        else j = pw4 ? __ldg(p32 + (size_t)k * (size_t)n + nn)
                     : (int)__ldg((const long long*)pinp + (size_t)k * (size_t)n + nn);
        cnt++;
        const float4 fv = reinterpret_cast<const float4*>(features)[(size_t)j * 16 + c4];
        const float4 wv = reinterpret_cast<const float4*>(weight)[k * 16 + c4];
        acc.x = fmaf(fv.x, wv.x, acc.x);
        acc.y = fmaf(fv.y, wv.y, acc.y);
        acc.z = fmaf(fv.z, wv.z, acc.z);
        acc.w = fmaf(fv.w, wv.w, acc.w);
    }

    // Output is write-once: stream it past L2.
    __stcs(reinterpret_cast<float4*>(out) + (size_t)nn * 16 + c4, acc);
}

extern "C" void kernel_launch(void* const* d_in, const int* in_sizes, int n_in,
                              void* d_out, int out_size)
{
    // Inputs in metadata order: features, weight, bias, pair_in, pair_out,
    // pair_mask. Identify by element count; the three 27*N arrays keep their
    // metadata order (pair_in, pair_out, pair_mask).
    int fi = -1, wi = -1, bi = -1;
    int big[3], nbig = 0;
    long long maxc = -1;
    for (int i = 0; i < n_in; i++)
        if ((long long)in_sizes[i] > maxc) { maxc = in_sizes[i]; fi = i; }
    for (int i = 0; i < n_in; i++) {
        if (i == fi) continue;
        if (in_sizes[i] == 64) bi = i;
        else if (in_sizes[i] == KTAPS * CCH) wi = i;
        else if (nbig < 3) big[nbig++] = i;
    }
    const float* features = (const float*)d_in[fi];
    const float* weight   = (const float*)d_in[wi];
    const float* bias     = (const float*)d_in[bi];
    const void*  pinp     = d_in[big[0]];   // pair_in
    // big[1] = pair_out (unused: scatter target == row under mask)
    const void*  maskp    = d_in[big[2]];   // pair_mask
    float* out = (float*)d_out;

    const int n = in_sizes[fi] / CCH;

    kbits<<<(n + 255) / 256, 256>>>(maskp, pinp, n);

    const int grid = (n + TILE - 1) / TILE;
    spdwconv_kernel<<<grid, THREADS>>>(features, weight, bias, pinp, out, n);
}